// round 4
// baseline (speedup 1.0000x reference)
#include <cuda_runtime.h>
#include <math.h>
#include <stdint.h>

// ---------------------------------------------------------------------------
// minGRU: out = exp(scan(log-space minGRU recurrence)) @ W_out
//   x:[4,4096,1024]  W_hg:[1024,4096]  W_out:[2048,1024]  out:[4,4096,1024] f32
//
// Stages:
//   1) sgemm: hg = x @ W_hg                          (fp32, 137 GFLOP)
//   2) elemwise: hg -> (log_values | log_coeffs) in place
//   3) chunked parallel scan over s (3 passes), h = exp(log_h)
//   4) sgemm: out = h @ W_out                        (fp32, 69 GFLOP)
// ---------------------------------------------------------------------------

#define S_LEN   4096
#define BATCH   4
#define DIM_IN  1024
#define DIN     2048            // dim_inner
#define NHG     4096            // 2*dim_inner
#define MROWS   (BATCH * S_LEN) // 16384
#define CHUNK   256
#define NCHUNK  (S_LEN / CHUNK) // 16

// ------------------------- device scratch (static) -------------------------
__device__ float g_hg[(size_t)MROWS * NHG];     // 256 MB: hg, then logv|logc in place
__device__ float g_h [(size_t)MROWS * DIN];     // 128 MB: exp(log_h)
__device__ float g_aggLC [BATCH * NCHUNK * DIN];
__device__ float g_aggLV [BATCH * NCHUNK * DIN];
__device__ float g_prefix[BATCH * NCHUNK * DIN];

#define NEG_BIG (-1e30f)

__device__ __forceinline__ float logaddexp_f(float a, float b) {
    float m = fmaxf(a, b);
    float d = fminf(a, b) - m;            // d <= 0 always
    return m + __logf(1.0f + __expf(d));
}

// ------------------------------- SGEMM -------------------------------------
// C[M,N] = A[M,K] @ B[K,N], all row-major fp32. Requires M%128==0, N%128==0,
// K%16==0 (true for both GEMMs here). 128x128 block tile, BK=16, 256 threads,
// 8x8 per-thread microtile, A stored transposed in smem with +1 pad.
#define BM 128
#define BN 128
#define BK 16
#define TM 8
#define TN 8

__global__ __launch_bounds__(256, 2)
void sgemm_kernel(const float* __restrict__ A, const float* __restrict__ B,
                  float* __restrict__ C, int M, int N, int K) {
    __shared__ float As[BK][BM + 1];   // transposed, padded (conflict-free stores)
    __shared__ float Bs[BK][BN];

    const int tid = threadIdx.x;
    const int tx  = tid & 15;          // 0..15
    const int ty  = tid >> 4;          // 0..15
    const int rowBlk = blockIdx.y * BM;
    const int colBlk = blockIdx.x * BN;

    // A-tile loader: 128x16 floats = 512 float4, 2 per thread
    const int a_r  = tid >> 2;         // 0..63 (and +64)
    const int a_c  = (tid & 3) * 4;    // 0,4,8,12
    // B-tile loader: 16x128 floats = 512 float4, 2 per thread
    const int b_r  = tid >> 5;         // 0..7 (and +8)
    const int b_c  = (tid & 31) * 4;   // 0..124

    float acc[TM][TN];
#pragma unroll
    for (int i = 0; i < TM; i++)
#pragma unroll
        for (int j = 0; j < TN; j++) acc[i][j] = 0.0f;

    for (int k0 = 0; k0 < K; k0 += BK) {
#pragma unroll
        for (int t = 0; t < 2; t++) {
            int r = a_r + t * 64;
            float4 v = *reinterpret_cast<const float4*>(
                &A[(size_t)(rowBlk + r) * K + k0 + a_c]);
            As[a_c + 0][r] = v.x;
            As[a_c + 1][r] = v.y;
            As[a_c + 2][r] = v.z;
            As[a_c + 3][r] = v.w;
        }
#pragma unroll
        for (int t = 0; t < 2; t++) {
            int r = b_r + t * 8;
            *reinterpret_cast<float4*>(&Bs[r][b_c]) =
                *reinterpret_cast<const float4*>(
                    &B[(size_t)(k0 + r) * N + colBlk + b_c]);
        }
        __syncthreads();

#pragma unroll
        for (int kk = 0; kk < BK; kk++) {
            float a[TM], b[TN];
#pragma unroll
            for (int i = 0; i < TM; i++) a[i] = As[kk][ty * TM + i];
#pragma unroll
            for (int j = 0; j < TN; j++) b[j] = Bs[kk][tx * TN + j];
#pragma unroll
            for (int i = 0; i < TM; i++)
#pragma unroll
                for (int j = 0; j < TN; j++)
                    acc[i][j] = fmaf(a[i], b[j], acc[i][j]);
        }
        __syncthreads();
    }

#pragma unroll
    for (int i = 0; i < TM; i++) {
        size_t crow = (size_t)(rowBlk + ty * TM + i) * N + colBlk + tx * TN;
#pragma unroll
        for (int j = 0; j < TN; j += 4) {
            float4 v = make_float4(acc[i][j], acc[i][j + 1],
                                   acc[i][j + 2], acc[i][j + 3]);
            *reinterpret_cast<float4*>(&C[crow + j]) = v;
        }
    }
}

// --------------------------- elementwise transform -------------------------
// hidden = hg[r][e], gate = hg[r][2048+e]
//   log_coeffs = -softplus(gate)
//   log_values = -softplus(-gate) + log_g(hidden)
// written in place: hg[r][e] <- log_values, hg[r][2048+e] <- log_coeffs
__global__ void elemwise_kernel() {
    size_t idx = (size_t)blockIdx.x * blockDim.x + threadIdx.x;
    if (idx >= (size_t)MROWS * DIN) return;
    size_t row = idx >> 11;        // /2048
    int    e   = (int)(idx & 2047);

    size_t base = row * NHG;
    float hidden = g_hg[base + e];
    float gate   = g_hg[base + DIN + e];

    // softplus(gate), numerically stable
    float sp_g = fmaxf(gate, 0.0f) + log1pf(__expf(-fabsf(gate)));
    float log_coeffs = -sp_g;
    float log_z = gate - sp_g;     // -softplus(-gate)

    // log_g(hidden) = x>=0 ? log(x+0.5) : x - log1p(exp(x))
    float lg;
    if (hidden >= 0.0f) lg = logf(hidden + 0.5f);
    else                lg = hidden - log1pf(__expf(hidden));

    g_hg[base + e]       = log_z + lg;    // log_values
    g_hg[base + DIN + e] = log_coeffs;
}

// ------------------------------- scan pass 1 -------------------------------
// Per (batch, chunk, channel): compute chunk aggregate operator (LC, LV):
//   h_out_log = logaddexp(LC + h_in_log, LV)
__global__ void scan_pass1_kernel() {
    int e = blockIdx.x * blockDim.x + threadIdx.x;   // 0..2047
    int c = blockIdx.y;
    int b = blockIdx.z;

    const float* base = g_hg + (size_t)(b * S_LEN + c * CHUNK) * NHG;
    float LC = 0.0f, LV = NEG_BIG;
#pragma unroll 4
    for (int s = 0; s < CHUNK; s++) {
        float lv = base[(size_t)s * NHG + e];
        float lc = base[(size_t)s * NHG + DIN + e];
        LC += lc;
        LV = logaddexp_f(lc + LV, lv);
    }
    int idx = (b * NCHUNK + c) * DIN + e;
    g_aggLC[idx] = LC;
    g_aggLV[idx] = LV;
}

// ------------------------------- scan pass 2 -------------------------------
// Sequential scan over the 16 chunk aggregates per channel; store the
// incoming state (log h) for each chunk.
__global__ void scan_pass2_kernel() {
    int idx = blockIdx.x * blockDim.x + threadIdx.x;  // 0..8191
    int b = idx >> 11;
    int e = idx & 2047;
    float st = NEG_BIG;                                // log h before chunk 0
#pragma unroll
    for (int c = 0; c < NCHUNK; c++) {
        int i = (b * NCHUNK + c) * DIN + e;
        float LC = g_aggLC[i];
        float LV = g_aggLV[i];
        g_prefix[i] = st;
        st = logaddexp_f(LC + st, LV);
    }
}

// ------------------------------- scan pass 3 -------------------------------
// Replay recurrence within each chunk from its prefix state; emit h = exp(.)
__global__ void scan_pass3_kernel() {
    int e = blockIdx.x * blockDim.x + threadIdx.x;
    int c = blockIdx.y;
    int b = blockIdx.z;

    float st = g_prefix[(b * NCHUNK + c) * DIN + e];
    const float* base = g_hg + (size_t)(b * S_LEN + c * CHUNK) * NHG;
    float* hout = g_h + (size_t)(b * S_LEN + c * CHUNK) * DIN;
#pragma unroll 4
    for (int s = 0; s < CHUNK; s++) {
        float lv = base[(size_t)s * NHG + e];
        float lc = base[(size_t)s * NHG + DIN + e];
        st = logaddexp_f(lc + st, lv);
        hout[(size_t)s * DIN + e] = expf(st);
    }
}

// ------------------------------- launcher -----------------------------------
extern "C" void kernel_launch(void* const* d_in, const int* in_sizes, int n_in,
                              void* d_out, int out_size) {
    const float* x    = (const float*)d_in[0];   // [4,4096,1024]
    const float* Whg  = (const float*)d_in[1];   // [1024,4096]
    const float* Wout = (const float*)d_in[2];   // [2048,1024]
    float* out = (float*)d_out;                  // [4,4096,1024]

    void* p_hg = nullptr;
    void* p_h  = nullptr;
    cudaGetSymbolAddress(&p_hg, g_hg);
    cudaGetSymbolAddress(&p_h,  g_h);
    float* hg = (float*)p_hg;
    float* h  = (float*)p_h;

    // 1) hg = x @ W_hg   : M=16384, N=4096, K=1024
    {
        dim3 grid(NHG / BN, MROWS / BM);
        sgemm_kernel<<<grid, 256>>>(x, Whg, hg, MROWS, NHG, DIM_IN);
    }

    // 2) elementwise -> (log_values | log_coeffs), in place
    {
        size_t n = (size_t)MROWS * DIN;
        int threads = 256;
        int blocks = (int)((n + threads - 1) / threads);
        elemwise_kernel<<<blocks, threads>>>();
    }

    // 3) chunked scan
    {
        dim3 grid1(DIN / 256, NCHUNK, BATCH);
        scan_pass1_kernel<<<grid1, 256>>>();
        scan_pass2_kernel<<<(BATCH * DIN) / 256, 256>>>();
        scan_pass3_kernel<<<grid1, 256>>>();
    }

    // 4) out = h @ W_out : M=16384, N=1024, K=2048
    {
        dim3 grid(DIM_IN / BN, MROWS / BM);
        sgemm_kernel<<<grid, 256>>>(h, Wout, out, MROWS, DIM_IN, DIN);
    }
}